// round 16
// baseline (speedup 1.0000x reference)
#include <cuda_runtime.h>
#include <cstdint>

#define BB 512
#define SS 4096
#define DD 128
#define KK 409
#define VV 6
#define NT 256
#define NT2 512
#define NW2 16            // warps per row CTA

// -------- global scratch (plain overwrites only; deterministic) --------
__device__ float g_sc [VV];
__device__ float g_U  [VV][64];    // U[v][n] = att_v . C1[:,n]

// ===========================================================================
// K1: 12 CTAs. blocks 0..5 -> score MLP per class; 6..11 -> attention+U.
// ===========================================================================
__global__ void __launch_bounds__(NT)
k1_tables(const float* __restrict__ emb,
          const float* __restrict__ W1, const float* __restrict__ b1,
          const float* __restrict__ W2, const float* __restrict__ b2,
          const float* __restrict__ W3, const float* __restrict__ b3,
          const float* __restrict__ A1, const float* __restrict__ a1,
          const float* __restrict__ A2, const float* __restrict__ a2,
          const float* __restrict__ C1) {
    const int tid = threadIdx.x;
    const int bid = blockIdx.x;
    __shared__ float e_s[DD];
    __shared__ float h1_s[64];
    __shared__ float h2_s[32];
    __shared__ float att_s[DD];

    const int v = (bid < VV) ? bid : bid - VV;
    if (tid < DD) e_s[tid] = emb[v * DD + tid];
    __syncthreads();

    if (bid < VV) {
        {   // h1: 4 threads/neuron, 8-way ILP
            const int n = tid >> 2, q = tid & 3;
            const int i0 = q * 32;
            float acc[8] = {0, 0, 0, 0, 0, 0, 0, 0};
            #pragma unroll
            for (int mm = 0; mm < 4; mm++)
                #pragma unroll
                for (int j = 0; j < 8; j++) {
                    const int i = i0 + mm * 8 + j;
                    acc[j] = fmaf(e_s[i], W1[i * 64 + n], acc[j]);
                }
            float s = ((acc[0] + acc[1]) + (acc[2] + acc[3]))
                    + ((acc[4] + acc[5]) + (acc[6] + acc[7]));
            s += __shfl_down_sync(0xFFFFFFFFu, s, 2);
            s += __shfl_down_sync(0xFFFFFFFFu, s, 1);
            if (q == 0) h1_s[n] = fmaxf(s + b1[n], 0.f);
        }
        __syncthreads();
        {   // h2: 8 threads/neuron
            const int n = tid >> 3, r = tid & 7;
            float acc[8];
            #pragma unroll
            for (int j = 0; j < 8; j++) {
                const int i = r + 8 * j;
                acc[j] = h1_s[i] * W2[i * 32 + n];
            }
            float s = ((acc[0] + acc[1]) + (acc[2] + acc[3]))
                    + ((acc[4] + acc[5]) + (acc[6] + acc[7]));
            s += __shfl_down_sync(0xFFFFFFFFu, s, 4);
            s += __shfl_down_sync(0xFFFFFFFFu, s, 2);
            s += __shfl_down_sync(0xFFFFFFFFu, s, 1);
            if (r == 0) h2_s[n] = fmaxf(s + b2[n], 0.f);
        }
        __syncthreads();
        if (tid < 32) {
            float s = h2_s[tid] * W3[tid];
            #pragma unroll
            for (int o = 16; o; o >>= 1) s += __shfl_down_sync(0xFFFFFFFFu, s, o);
            if (tid == 0) g_sc[v] = 1.f / (1.f + expf(-(s + b3[0])));
        }
    } else {
        {   // g: 4 threads/neuron
            const int n = tid >> 2, q = tid & 3;
            const int i0 = q * 32;
            float acc[8] = {0, 0, 0, 0, 0, 0, 0, 0};
            #pragma unroll
            for (int mm = 0; mm < 4; mm++)
                #pragma unroll
                for (int j = 0; j < 8; j++) {
                    const int i = i0 + mm * 8 + j;
                    acc[j] = fmaf(e_s[i], A1[i * 64 + n], acc[j]);
                }
            float s = ((acc[0] + acc[1]) + (acc[2] + acc[3]))
                    + ((acc[4] + acc[5]) + (acc[6] + acc[7]));
            s += __shfl_down_sync(0xFFFFFFFFu, s, 2);
            s += __shfl_down_sync(0xFFFFFFFFu, s, 1);
            if (q == 0) h1_s[n] = fmaxf(s + a1[n], 0.f);   // g
        }
        __syncthreads();
        {   // att: 2 threads per output dim
            const int d = tid >> 1, q = tid & 1;
            const int j0 = q * 32;
            float acc[8] = {0, 0, 0, 0, 0, 0, 0, 0};
            #pragma unroll
            for (int mm = 0; mm < 4; mm++)
                #pragma unroll
                for (int jj = 0; jj < 8; jj++) {
                    const int j = j0 + mm * 8 + jj;
                    acc[jj] = fmaf(h1_s[j], A2[j * DD + d], acc[jj]);
                }
            float s = ((acc[0] + acc[1]) + (acc[2] + acc[3]))
                    + ((acc[4] + acc[5]) + (acc[6] + acc[7]));
            s += __shfl_down_sync(0xFFFFFFFFu, s, 1);
            if (q == 0) att_s[d] = s + a2[d];
        }
        __syncthreads();
        {   // U[v][n] = att . C1[:,n]
            const int n = tid >> 2, q = tid & 3;
            const int i0 = q * 32;
            float acc[8] = {0, 0, 0, 0, 0, 0, 0, 0};
            #pragma unroll
            for (int mm = 0; mm < 4; mm++)
                #pragma unroll
                for (int j = 0; j < 8; j++) {
                    const int i = i0 + mm * 8 + j;
                    acc[j] = fmaf(att_s[i], C1[i * 64 + n], acc[j]);
                }
            float s = ((acc[0] + acc[1]) + (acc[2] + acc[3]))
                    + ((acc[4] + acc[5]) + (acc[6] + acc[7]));
            s += __shfl_down_sync(0xFFFFFFFFu, s, 2);
            s += __shfl_down_sync(0xFFFFFFFFu, s, 1);
            if (q == 0) g_U[v][n] = s;
        }
    }
}

// ===========================================================================
// K2: one 512-thread CTA per row (16 warps). Warp w owns 256 consecutive
// tokens; lane owns 8 consecutive tokens (2 int4). ONE packed-u64 scan,
// base-folded shfl-free scatter, fs writes pre-barrier.
// ===========================================================================
__global__ void __launch_bounds__(NT2, 2)
k2_row(const int* __restrict__ x,
       const float* __restrict__ c1, const float* __restrict__ C2,
       const float* __restrict__ c2, float* __restrict__ out) {
    const int row = blockIdx.x;
    const int tid = threadIdx.x;
    const int w = tid >> 5, lane = tid & 31;
    const int cls = (lane < VV) ? lane : 0;

    __shared__ unsigned long long wtot_s[NW2];
    __shared__ int   selcnt_sm[VV];                // tie path only
    __shared__ float scf_sm[VV];                   // tie path only

    float* __restrict__ top_out = out + BB;
    float* __restrict__ fs_out  = out + BB + (size_t)BB * KK;

    const float scv = g_sc[cls];                   // 6 hot addresses

    // ---- loads: lane owns 8 consecutive tokens (2 int4, 32B) ----
    const int4* rp = reinterpret_cast<const int4*>(x + (size_t)row * SS);
    const int i0 = w * 64 + lane * 2;              // int4 index
    const int4 a0 = rp[i0];
    const int4 a1v = rp[i0 + 1];

    // ---- packed per-thread count (10 bits/class; warp max 256 fits) ----
    unsigned long long c = 0;
    c += 1ULL << (10 * a0.x);  c += 1ULL << (10 * a0.y);
    c += 1ULL << (10 * a0.z);  c += 1ULL << (10 * a0.w);
    c += 1ULL << (10 * a1v.x); c += 1ULL << (10 * a1v.y);
    c += 1ULL << (10 * a1v.z); c += 1ULL << (10 * a1v.w);

    // ---- fs writes (LUT via shfl), pre-barrier ----
    {
        float4* fo = reinterpret_cast<float4*>(fs_out + (size_t)row * SS);
        float4 f;
        f.x = __shfl_sync(0xFFFFFFFFu, scv, a0.x);
        f.y = __shfl_sync(0xFFFFFFFFu, scv, a0.y);
        f.z = __shfl_sync(0xFFFFFFFFu, scv, a0.z);
        f.w = __shfl_sync(0xFFFFFFFFu, scv, a0.w); fo[i0] = f;
        f.x = __shfl_sync(0xFFFFFFFFu, scv, a1v.x);
        f.y = __shfl_sync(0xFFFFFFFFu, scv, a1v.y);
        f.z = __shfl_sync(0xFFFFFFFFu, scv, a1v.z);
        f.w = __shfl_sync(0xFFFFFFFFu, scv, a1v.w); fo[i0 + 1] = f;
    }

    // ---- single inclusive warp scan (position order) ----
    unsigned long long incl = c;
    #pragma unroll
    for (int off = 1; off < 32; off <<= 1) {
        const unsigned long long n = __shfl_up_sync(0xFFFFFFFFu, incl, off);
        if (lane >= off) incl += n;
    }
    unsigned long long E = incl - c;               // exclusive in-warp prefix
    if (lane == 31) wtot_s[w] = incl;
    __syncthreads();

    // ---- per-warp lanes 0..5: class totals, warp prefix, base, eq-mask ----
    int T = 0, wpre = 0;
    #pragma unroll
    for (int i = 0; i < NW2; i++) {
        const int e = (int)((wtot_s[i] >> (10 * cls)) & 1023ULL);
        T += e;
        if (i < w) wpre += e;
    }
    int b = 0; unsigned m = 0;
    #pragma unroll
    for (int u = 0; u < VV; u++) {
        const int   tu = __shfl_sync(0xFFFFFFFFu, T,   u);
        const float su = __shfl_sync(0xFFFFFFFFu, scv, u);
        if (su > scv) b += tu;
        if (su == scv) m |= 1u << u;
    }
    const bool tie =
        __ballot_sync(0xFFFFFFFFu, (lane < VV) && (m != (1u << lane))) != 0;

    const size_t obase = (size_t)row * KK;
    const int p0 = w * 256 + lane * 8;

    if (!tie) {
        // ---- fold clamped base into the packed prefix (shfl-free scatter) --
        // Bc = min(b+wpre, K): exact for B<K; B>=K keeps r>=K (skipped);
        // field bound 409+256=665 < 1024 (no cross-field carry).
        const int B = b + wpre;
        const int Bc = (B < KK) ? B : KK;
        unsigned long long Bp = 0;
        #pragma unroll
        for (int u = 0; u < VV; u++)
            Bp |= (unsigned long long)__shfl_sync(0xFFFFFFFFu, Bc, u) << (10 * u);
        E += Bp;

        const int ta[8] = {a0.x, a0.y, a0.z, a0.w, a1v.x, a1v.y, a1v.z, a1v.w};
        #pragma unroll
        for (int j = 0; j < 8; j++) {
            const int sh = 10 * ta[j];
            const int r = (int)((E >> sh) & 1023ULL);
            E += 1ULL << sh;
            if (r < KK) top_out[obase + r] = (float)(p0 + j);
        }
        // ---- warp-0 tail: analytic selcnt + classifier, barrier-free ----
        if (w == 0) {
            int sel = KK - b;
            sel = sel < 0 ? 0 : (sel > T ? T : sel);       // lanes 0..5 valid
            const float cnt = (float)sel * (1.0f / (float)KK);
            float acc0 = c1[lane], acc1 = c1[lane + 32];
            #pragma unroll
            for (int v = 0; v < VV; v++) {
                const float cv = __shfl_sync(0xFFFFFFFFu, cnt, v);
                acc0 = fmaf(cv, g_U[v][lane],      acc0);
                acc1 = fmaf(cv, g_U[v][lane + 32], acc1);
            }
            float s = fmaxf(acc0, 0.f) * C2[lane] + fmaxf(acc1, 0.f) * C2[lane + 32];
            #pragma unroll
            for (int o = 16; o; o >>= 1) s += __shfl_down_sync(0xFFFFFFFFu, s, o);
            if (lane == 0) out[row] = 1.f / (1.f + expf(-(s + c2[0])));
        }
    } else {
        // ---- tie path: exact lax.top_k mask semantics (dead in practice) ----
        if (tid < VV) selcnt_sm[tid] = 0;
        __syncthreads();
        int ls[VV] = {0, 0, 0, 0, 0, 0};
        const int ta[8] = {a0.x, a0.y, a0.z, a0.w, a1v.x, a1v.y, a1v.z, a1v.w};
        #pragma unroll
        for (int j = 0; j < 8; j++) {
            const int v = ta[j];
            const unsigned mv = __shfl_sync(0xFFFFFFFFu, m, v);
            int r = __shfl_sync(0xFFFFFFFFu, b, v);
            #pragma unroll
            for (int u = 0; u < VV; u++)
                if ((mv >> u) & 1u)
                    r += __shfl_sync(0xFFFFFFFFu, wpre, u)
                       + (int)((E >> (10 * u)) & 1023ULL);
            E += 1ULL << (10 * v);
            if (r < KK) {
                top_out[obase + r] = (float)(p0 + j);
                #pragma unroll
                for (int u = 0; u < VV; u++) ls[u] += (v == u);
            }
        }
        #pragma unroll
        for (int u = 0; u < VV; u++) {
            #pragma unroll
            for (int o = 16; o; o >>= 1) ls[u] += __shfl_down_sync(0xFFFFFFFFu, ls[u], o);
        }
        if (lane == 0) {
            #pragma unroll
            for (int u = 0; u < VV; u++)
                if (ls[u]) atomicAdd(&selcnt_sm[u], ls[u]);
        }
        __syncthreads();
        if (tid < VV) scf_sm[tid] = (float)selcnt_sm[tid];
        __syncthreads();
        if (w == 0) {
            const float cnt = scf_sm[cls] * (1.0f / (float)KK);
            float acc0 = c1[lane], acc1 = c1[lane + 32];
            #pragma unroll
            for (int v = 0; v < VV; v++) {
                const float cv = __shfl_sync(0xFFFFFFFFu, cnt, v);
                acc0 = fmaf(cv, g_U[v][lane],      acc0);
                acc1 = fmaf(cv, g_U[v][lane + 32], acc1);
            }
            float s = fmaxf(acc0, 0.f) * C2[lane] + fmaxf(acc1, 0.f) * C2[lane + 32];
            #pragma unroll
            for (int o = 16; o; o >>= 1) s += __shfl_down_sync(0xFFFFFFFFu, s, o);
            if (lane == 0) out[row] = 1.f / (1.f + expf(-(s + c2[0])));
        }
    }
}

// ===========================================================================
extern "C" void kernel_launch(void* const* d_in, const int* in_sizes, int n_in,
                              void* d_out, int out_size) {
    const int*   x   = (const int*)  d_in[0];
    const float* emb = (const float*)d_in[1];
    const float* W1  = (const float*)d_in[2];
    const float* b1  = (const float*)d_in[3];
    const float* W2  = (const float*)d_in[4];
    const float* b2  = (const float*)d_in[5];
    const float* W3  = (const float*)d_in[6];
    const float* b3  = (const float*)d_in[7];
    const float* A1  = (const float*)d_in[8];
    const float* a1  = (const float*)d_in[9];
    const float* A2  = (const float*)d_in[10];
    const float* a2  = (const float*)d_in[11];
    const float* C1  = (const float*)d_in[12];
    const float* c1  = (const float*)d_in[13];
    const float* C2  = (const float*)d_in[14];
    const float* c2  = (const float*)d_in[15];
    float* out = (float*)d_out;

    k1_tables<<<2 * VV, NT>>>(emb, W1, b1, W2, b2, W3, b3, A1, a1, A2, a2, C1);
    k2_row<<<BB, NT2>>>(x, c1, C2, c2, out);
}